// round 3
// baseline (speedup 1.0000x reference)
#include <cuda_runtime.h>
#include <cstdint>

#define NB   32
#define NS   512
#define NBLK 128          // persistent scan grid (<=148 SMs -> co-resident)
#define NW   (NBLK * 8)   // total warps in scan grid

// ------------------------- device scratch (no allocs allowed) ---------------
__device__ float g_xg[16384 * 3072];   // gate preactivations (max 3H = 3072)
__device__ float g_y0[16384 * 512];
__device__ float g_y1[16384 * 1024];
__device__ float g_y2[16384 * 512];
__device__ float g_h4T [32 * 1024];    // h,  layout: [(k>>2)][b][k&3]
__device__ float g_rh4T[32 * 1024];    // r*h, same layout
__device__ float g_zJ  [1024 * 32];    // z,  layout: [j][b]

// ------------------------- grid barrier (sense reversal, self-reset) --------
__device__ int          g_bar_count = 0;
__device__ volatile int g_bar_phase = 0;

__device__ __forceinline__ void gbar() {
    __syncthreads();
    if (threadIdx.x == 0) {
        __threadfence();                          // data fence + L1 invalidate
        int ph = g_bar_phase;
        if (atomicAdd(&g_bar_count, 1) == NBLK - 1) {
            g_bar_count = 0;
            __threadfence();
            g_bar_phase = ph ^ 1;
        } else {
            while (g_bar_phase == ph) { __nanosleep(64); }
        }
        __threadfence();                          // acquire + L1 invalidate
    }
    __syncthreads();
}

__device__ __forceinline__ float sigm(float x) {
    return 1.0f / (1.0f + __expf(-x));
}

// ------------------------- GEMM: C[M,N] = A[M,K] * B[N,K]^T + bias ----------
// 64x64x16 tiles, 256 threads, 4x4 per thread. M%64==0, N%64==0, K%16==0.
#define BM 64
#define BN 64
#define BK 16

template <bool RELU>
__global__ void __launch_bounds__(256)
gemm_tn(const float* __restrict__ A, const float* __restrict__ B,
        const float* __restrict__ bias, float* __restrict__ C,
        int M, int N, int K)
{
    __shared__ float As[BK][BM + 4];
    __shared__ float Bs[BK][BN + 4];

    const int tid = threadIdx.x;
    const int tx  = tid & 15;       // 0..15 -> 4 cols each
    const int ty  = tid >> 4;       // 0..15 -> 4 rows each
    const int m0  = blockIdx.y * BM;
    const int n0  = blockIdx.x * BN;

    const int lrow = tid >> 2;          // 0..63
    const int lk   = (tid & 3) * 4;     // 0,4,8,12

    float acc[4][4] = {};

    for (int k0 = 0; k0 < K; k0 += BK) {
        float4 a4 = *(const float4*)(A + (size_t)(m0 + lrow) * K + k0 + lk);
        float4 b4 = *(const float4*)(B + (size_t)(n0 + lrow) * K + k0 + lk);
        As[lk + 0][lrow] = a4.x; As[lk + 1][lrow] = a4.y;
        As[lk + 2][lrow] = a4.z; As[lk + 3][lrow] = a4.w;
        Bs[lk + 0][lrow] = b4.x; Bs[lk + 1][lrow] = b4.y;
        Bs[lk + 2][lrow] = b4.z; Bs[lk + 3][lrow] = b4.w;
        __syncthreads();
        #pragma unroll
        for (int kk = 0; kk < BK; kk++) {
            float am[4], bn[4];
            #pragma unroll
            for (int i = 0; i < 4; i++) am[i] = As[kk][ty * 4 + i];
            #pragma unroll
            for (int j = 0; j < 4; j++) bn[j] = Bs[kk][tx * 4 + j];
            #pragma unroll
            for (int i = 0; i < 4; i++)
                #pragma unroll
                for (int j = 0; j < 4; j++)
                    acc[i][j] = fmaf(am[i], bn[j], acc[i][j]);
        }
        __syncthreads();
    }

    #pragma unroll
    for (int i = 0; i < 4; i++) {
        const int m = m0 + ty * 4 + i;
        #pragma unroll
        for (int j = 0; j < 4; j++) {
            const int n = n0 + tx * 4 + j;
            float v = acc[i][j] + bias[n];
            if (RELU) v = fmaxf(v, 0.0f);
            C[(size_t)m * N + n] = v;
        }
    }
}

// ------------------------- persistent GRU scan ------------------------------
// lane = batch (B == 32). Warp gw handles columns j = gw, gw+NW, ...
// Phase 1: r,z gates (stores r*h and z). Phase 2: n gate + h update + y.
template <int H>
__global__ void __launch_bounds__(256, 1)
gru_scan(const float* __restrict__ xg, const float* __restrict__ Wh,
         const float* __restrict__ h0, float* __restrict__ y)
{
    const int tid  = threadIdx.x;
    const int lane = tid & 31;
    const int gw   = blockIdx.x * 8 + (tid >> 5);
    const int K4   = H / 4;

    // init h = broadcast(h0) in interleaved layout
    for (int idx = blockIdx.x * 256 + tid; idx < 32 * H; idx += NBLK * 256) {
        const int k = idx >> 5, b = idx & 31;
        g_h4T[((k >> 2) * 128) + b * 4 + (k & 3)] = h0[k];
    }
    gbar();

    const float4* Wr4 = (const float4*)(Wh);
    const float4* Wz4 = (const float4*)(Wh + (size_t)H * H);
    const float4* Wn4 = (const float4*)(Wh + (size_t)2 * H * H);

    for (int t = 0; t < NS; t++) {
        // ---------------- phase 1: r, z ----------------
        for (int j = gw; j < H; j += NW) {
            const float4* h4p = ((const float4*)g_h4T) + lane;
            const float4* wr  = Wr4 + (size_t)j * K4;
            const float4* wz  = Wz4 + (size_t)j * K4;
            float ar0 = 0.f, ar1 = 0.f, az0 = 0.f, az1 = 0.f;
            #pragma unroll 4
            for (int k4 = 0; k4 < K4; k4++) {
                float4 h4 = h4p[k4 * 32];
                float4 w  = __ldg(wr + k4);
                ar0 = fmaf(h4.x, w.x, ar0); ar1 = fmaf(h4.y, w.y, ar1);
                ar0 = fmaf(h4.z, w.z, ar0); ar1 = fmaf(h4.w, w.w, ar1);
                w = __ldg(wz + k4);
                az0 = fmaf(h4.x, w.x, az0); az1 = fmaf(h4.y, w.y, az1);
                az0 = fmaf(h4.z, w.z, az0); az1 = fmaf(h4.w, w.w, az1);
            }
            const float* xrow = xg + ((size_t)(lane * NS + t)) * 3 * H;
            const float r = sigm(xrow[j]     + ar0 + ar1);
            const float z = sigm(xrow[H + j] + az0 + az1);
            const int ofs = ((j >> 2) * 128) + lane * 4 + (j & 3);
            g_rh4T[ofs]        = r * g_h4T[ofs];
            g_zJ[j * 32 + lane] = z;
        }
        gbar();
        // ---------------- phase 2: n + update ----------------
        for (int j = gw; j < H; j += NW) {
            const float4* rh4p = ((const float4*)g_rh4T) + lane;
            const float4* wn   = Wn4 + (size_t)j * K4;
            float an0 = 0.f, an1 = 0.f;
            #pragma unroll 4
            for (int k4 = 0; k4 < K4; k4++) {
                float4 h4 = rh4p[k4 * 32];
                float4 w  = __ldg(wn + k4);
                an0 = fmaf(h4.x, w.x, an0); an1 = fmaf(h4.y, w.y, an1);
                an0 = fmaf(h4.z, w.z, an0); an1 = fmaf(h4.w, w.w, an1);
            }
            const float xn = xg[((size_t)(lane * NS + t)) * 3 * H + 2 * H + j];
            const float n  = tanhf(xn + an0 + an1);
            const int ofs  = ((j >> 2) * 128) + lane * 4 + (j & 3);
            const float hold = g_h4T[ofs];
            const float z    = g_zJ[j * 32 + lane];
            const float hnew = (1.0f - z) * hold + z * n;
            g_h4T[ofs] = hnew;
            y[((size_t)(lane * NS + t)) * H + j] = hnew;
        }
        gbar();
    }
}

// ------------------------- launch ------------------------------------------
extern "C" void kernel_launch(void* const* d_in, const int* in_sizes, int n_in,
                              void* d_out, int out_size)
{
    (void)in_sizes; (void)n_in; (void)out_size;
    const float* x   = (const float*)d_in[0];
    const float* Wi0 = (const float*)d_in[1];
    const float* Wh0 = (const float*)d_in[2];
    const float* bh0 = (const float*)d_in[3];
    const float* h00 = (const float*)d_in[4];
    const float* Wi1 = (const float*)d_in[5];
    const float* Wh1 = (const float*)d_in[6];
    const float* bh1 = (const float*)d_in[7];
    const float* h01 = (const float*)d_in[8];
    const float* Wi2 = (const float*)d_in[9];
    const float* Wh2 = (const float*)d_in[10];
    const float* bh2 = (const float*)d_in[11];
    const float* h02 = (const float*)d_in[12];
    const float* Wo  = (const float*)d_in[13];
    const float* bo  = (const float*)d_in[14];
    float* out = (float*)d_out;

    float *xg_p, *y0_p, *y1_p, *y2_p;
    cudaGetSymbolAddress((void**)&xg_p, g_xg);
    cudaGetSymbolAddress((void**)&y0_p, g_y0);
    cudaGetSymbolAddress((void**)&y1_p, g_y1);
    cudaGetSymbolAddress((void**)&y2_p, g_y2);

    const int M = NB * NS;  // 16384

    // layer 0: I=256 -> H=512
    gemm_tn<false><<<dim3(1536 / BN, M / BM), 256>>>(x, Wi0, bh0, xg_p, M, 1536, 256);
    gru_scan<512><<<NBLK, 256>>>(xg_p, Wh0, h00, y0_p);
    // layer 1: 512 -> 1024
    gemm_tn<false><<<dim3(3072 / BN, M / BM), 256>>>(y0_p, Wi1, bh1, xg_p, M, 3072, 512);
    gru_scan<1024><<<NBLK, 256>>>(xg_p, Wh1, h01, y1_p);
    // layer 2: 1024 -> 512
    gemm_tn<false><<<dim3(1536 / BN, M / BM), 256>>>(y1_p, Wi2, bh2, xg_p, M, 1536, 1024);
    gru_scan<512><<<NBLK, 256>>>(xg_p, Wh2, h02, y2_p);
    // output head: 512 -> 256, ReLU
    gemm_tn<true><<<dim3(256 / BN, M / BM), 256>>>(y2_p, Wo, bo, out, M, 256, 512);
}

// round 4
// speedup vs baseline: 1.8458x; 1.8458x over previous
#include <cuda_runtime.h>
#include <cstdint>

#define NB   32
#define NS   512
#define NBLK 128

// ------------------------- device scratch (no allocs allowed) ---------------
__device__ float g_xg[16384 * 3072];   // transposed: [(t*3H + n)*32 + b]
__device__ float g_y0[16384 * 512];
__device__ float g_y1[16384 * 1024];
__device__ float g_y2[16384 * 512];
__device__ float g_h [32 * 1024];      // k-interleaved: [(k>>2)*128 + b*4 + (k&3)]
__device__ float g_rh[32 * 1024];
__device__ unsigned g_bar;             // monotonic grid-barrier counter

__device__ __forceinline__ unsigned su32(const void* p) {
    return (unsigned)__cvta_generic_to_shared(p);
}
__device__ __forceinline__ float sigm(float x) {
    return 1.0f / (1.0f + __expf(-x));
}

// Grid barrier: release-atomic arrive + acquire-load spin. No __threadfence,
// no CCTL.IVALL -> L1 (weights) stays warm across steps. Monotonic counter,
// wrap-safe compare; base re-read at kernel start (stream order guarantees
// the previous launch fully drained), so graph replays are safe.
__device__ __forceinline__ void gbar(unsigned& tgt) {
    __syncthreads();
    if (threadIdx.x == 0) {
        asm volatile("red.release.gpu.global.add.u32 [%0], %1;"
                     :: "l"(&g_bar), "r"(1u) : "memory");
        tgt += NBLK;
        unsigned v;
        do {
            asm volatile("ld.acquire.gpu.global.u32 %0, [%1];"
                         : "=r"(v) : "l"(&g_bar) : "memory");
        } while ((int)(v - tgt) < 0);
    }
    __syncthreads();
}

__device__ __forceinline__ void mwait(unsigned mb, unsigned par) {
    asm volatile(
        "{\n\t.reg .pred P;\n"
        "LW_%=:\n\t"
        "mbarrier.try_wait.parity.shared.b64 P, [%0], %1;\n\t"
        "@!P bra LW_%=;\n\t}"
        :: "r"(mb), "r"(par) : "memory");
}

__device__ __forceinline__ void bulk_g2s(unsigned sdst, const void* gsrc,
                                         unsigned bytes, unsigned mb) {
    asm volatile(
        "cp.async.bulk.shared::cluster.global.mbarrier::complete_tx::bytes "
        "[%0], [%1], %2, [%3];"
        :: "r"(sdst), "l"(gsrc), "r"(bytes), "r"(mb) : "memory");
}
__device__ __forceinline__ void expect_tx(unsigned mb, unsigned bytes) {
    asm volatile("mbarrier.arrive.expect_tx.shared.b64 _, [%0], %1;"
                 :: "r"(mb), "r"(bytes) : "memory");
}

// ------------------------- GEMM: C = A[M,K] * B[N,K]^T + bias ---------------
#define BM 64
#define BN 64
#define BK 16

template <bool RELU, bool TSTORE>
__global__ void __launch_bounds__(256)
gemm_tn(const float* __restrict__ A, const float* __restrict__ B,
        const float* __restrict__ bias, float* __restrict__ C,
        int M, int N, int K)
{
    __shared__ float As[BK][BM + 4];
    __shared__ float Bs[BK][BN + 4];

    const int tid = threadIdx.x;
    const int tx  = tid & 15;
    const int ty  = tid >> 4;
    const int m0  = blockIdx.y * BM;
    const int n0  = blockIdx.x * BN;
    const int lrow = tid >> 2;
    const int lk   = (tid & 3) * 4;

    float acc[4][4] = {};

    for (int k0 = 0; k0 < K; k0 += BK) {
        float4 a4 = *(const float4*)(A + (size_t)(m0 + lrow) * K + k0 + lk);
        float4 b4 = *(const float4*)(B + (size_t)(n0 + lrow) * K + k0 + lk);
        As[lk + 0][lrow] = a4.x; As[lk + 1][lrow] = a4.y;
        As[lk + 2][lrow] = a4.z; As[lk + 3][lrow] = a4.w;
        Bs[lk + 0][lrow] = b4.x; Bs[lk + 1][lrow] = b4.y;
        Bs[lk + 2][lrow] = b4.z; Bs[lk + 3][lrow] = b4.w;
        __syncthreads();
        #pragma unroll
        for (int kk = 0; kk < BK; kk++) {
            float am[4], bn[4];
            #pragma unroll
            for (int i = 0; i < 4; i++) am[i] = As[kk][ty * 4 + i];
            #pragma unroll
            for (int j = 0; j < 4; j++) bn[j] = Bs[kk][tx * 4 + j];
            #pragma unroll
            for (int i = 0; i < 4; i++)
                #pragma unroll
                for (int j = 0; j < 4; j++)
                    acc[i][j] = fmaf(am[i], bn[j], acc[i][j]);
        }
        __syncthreads();
    }

    #pragma unroll
    for (int i = 0; i < 4; i++) {
        const int m = m0 + ty * 4 + i;
        #pragma unroll
        for (int j = 0; j < 4; j++) {
            const int n = n0 + tx * 4 + j;
            float v = acc[i][j] + bias[n];
            if (RELU) v = fmaxf(v, 0.0f);
            if (TSTORE) {
                // transposed store for scan consumption: [(t*N + n)*32 + b]
                const int t = m & (NS - 1);
                const int b = m >> 9;
                C[((size_t)t * N + n) * 32 + b] = v;
            } else {
                C[(size_t)m * N + n] = v;
            }
        }
    }
}

// ------------------------- persistent GRU scan ------------------------------
// 128 blocks x 256 threads, all co-resident. lane = batch.
// Block owns contiguous column slice J0..J0+JB. Warps split (column-group,
// K-half); K-halves reduced through smem. State (h, rh) broadcast via
// cp.async.bulk into smem each phase; weights L1-resident (never flushed).
template <int H>
__global__ void __launch_bounds__(256, 1)
gru_scan(const float* __restrict__ xg, const float* __restrict__ Wh,
         const float* __restrict__ h0, float* __restrict__ y)
{
    constexpr int JB  = (H == 1024) ? 8 : 4;   // columns per block
    constexpr int JT  = JB / 4;                // columns per warp (2 or 1)
    constexpr int K4  = H / 4;
    constexpr int K4H = K4 / 2;                // k4-iters per K-half
    constexpr unsigned STATE_B = 32u * H * 4u;

    extern __shared__ float sm[];
    float* sm_state = sm;                       // [32*H]
    float* sm_z     = sm + 32 * H;              // [JB*32]
    float* sm_hold  = sm_z + JB * 32;
    float* sm_yb    = sm_hold + JB * 32;
    float* sm_red   = sm_yb + JB * 32;          // [JB*2*32]
    __shared__ __align__(8) unsigned long long mbar;

    const int tid  = threadIdx.x;
    const int lane = tid & 31;
    const int w    = tid >> 5;
    const int kh   = w >> 2;                    // K-half
    const int wq   = w & 3;                     // column-group
    const int J0   = blockIdx.x * JB;
    const int jbase = J0 + wq * JT;
    const unsigned mb = su32(&mbar);

    unsigned tgt = 0;
    if (tid == 0) {
        asm volatile("ld.acquire.gpu.global.u32 %0, [%1];"
                     : "=r"(tgt) : "l"(&g_bar) : "memory");
        asm volatile("mbarrier.init.shared.b64 [%0], 1;" :: "r"(mb) : "memory");
    }
    __syncthreads();

    // init h = broadcast(h0), interleaved layout, via .cg (L2-coherent)
    for (int idx = blockIdx.x * 256 + tid; idx < 32 * H; idx += NBLK * 256) {
        const int k = idx >> 5, b = idx & 31;
        __stcg(&g_h[(k >> 2) * 128 + b * 4 + (k & 3)], h0[k]);
    }
    gbar(tgt);
    if (tid == 0) { expect_tx(mb, STATE_B); bulk_g2s(su32(sm_state), g_h, STATE_B, mb); }

    const float4* W4  = (const float4*)Wh;
    const float4* hs4 = (const float4*)sm_state;
    unsigned par = 0;

    for (int t = 0; t < NS; t++) {
        mwait(mb, par); par ^= 1;               // h staged in smem

        // ================= phase 1: r, z =================
        float ar[JT], az[JT], xr[JT], xz[JT];
        #pragma unroll
        for (int i = 0; i < JT; i++) { ar[i] = 0.f; az[i] = 0.f; }
        if (kh == 0) {
            #pragma unroll
            for (int i = 0; i < JT; i++) {
                xr[i] = xg[((size_t)t * 3 * H + jbase + i) * 32 + lane];
                xz[i] = xg[((size_t)t * 3 * H + H + jbase + i) * 32 + lane];
            }
        }
        {
            const int k4b = kh * K4H;
            #pragma unroll 4
            for (int k4 = 0; k4 < K4H; k4++) {
                const float4 h4 = hs4[(k4b + k4) * 32 + lane];
                #pragma unroll
                for (int i = 0; i < JT; i++) {
                    const float4 wr = __ldg(W4 + (size_t)(jbase + i) * K4 + k4b + k4);
                    const float4 wz = __ldg(W4 + ((size_t)H + jbase + i) * K4 + k4b + k4);
                    ar[i] = fmaf(h4.x, wr.x, fmaf(h4.y, wr.y,
                            fmaf(h4.z, wr.z, fmaf(h4.w, wr.w, ar[i]))));
                    az[i] = fmaf(h4.x, wz.x, fmaf(h4.y, wz.y,
                            fmaf(h4.z, wz.z, fmaf(h4.w, wz.w, az[i]))));
                }
            }
        }
        if (kh == 1) {
            #pragma unroll
            for (int i = 0; i < JT; i++) {
                sm_red[((wq * JT + i) * 2 + 0) * 32 + lane] = ar[i];
                sm_red[((wq * JT + i) * 2 + 1) * 32 + lane] = az[i];
            }
        }
        __syncthreads();
        if (kh == 0) {
            #pragma unroll
            for (int i = 0; i < JT; i++) {
                const int j  = jbase + i;
                const int jj = wq * JT + i;
                const float r = sigm(xr[i] + ar[i] + sm_red[(jj * 2 + 0) * 32 + lane]);
                const float z = sigm(xz[i] + az[i] + sm_red[(jj * 2 + 1) * 32 + lane]);
                const float hold = sm_state[(j >> 2) * 128 + lane * 4 + (j & 3)];
                __stcg(&g_rh[(j >> 2) * 128 + lane * 4 + (j & 3)], r * hold);
                sm_z[jj * 32 + lane]    = z;
                sm_hold[jj * 32 + lane] = hold;
            }
        }
        gbar(tgt);                               // rh globally complete
        if (tid == 0) { expect_tx(mb, STATE_B); bulk_g2s(su32(sm_state), g_rh, STATE_B, mb); }
        mwait(mb, par); par ^= 1;                // rh staged in smem

        // ================= phase 2: n + update =================
        float an[JT], xn[JT];
        #pragma unroll
        for (int i = 0; i < JT; i++) an[i] = 0.f;
        if (kh == 0) {
            #pragma unroll
            for (int i = 0; i < JT; i++)
                xn[i] = xg[((size_t)t * 3 * H + 2 * H + jbase + i) * 32 + lane];
        }
        {
            const int k4b = kh * K4H;
            #pragma unroll 4
            for (int k4 = 0; k4 < K4H; k4++) {
                const float4 r4 = hs4[(k4b + k4) * 32 + lane];
                #pragma unroll
                for (int i = 0; i < JT; i++) {
                    const float4 wn = __ldg(W4 + ((size_t)2 * H + jbase + i) * K4 + k4b + k4);
                    an[i] = fmaf(r4.x, wn.x, fmaf(r4.y, wn.y,
                            fmaf(r4.z, wn.z, fmaf(r4.w, wn.w, an[i]))));
                }
            }
        }
        if (kh == 1) {
            #pragma unroll
            for (int i = 0; i < JT; i++)
                sm_red[(wq * JT + i) * 32 + lane] = an[i];
        }
        __syncthreads();
        if (kh == 0) {
            #pragma unroll
            for (int i = 0; i < JT; i++) {
                const int j  = jbase + i;
                const int jj = wq * JT + i;
                const float n    = tanhf(xn[i] + an[i] + sm_red[jj * 32 + lane]);
                const float z    = sm_z[jj * 32 + lane];
                const float hold = sm_hold[jj * 32 + lane];
                const float hnew = fmaf(z, n - hold, hold);  // (1-z)h + z n
                __stcg(&g_h[(j >> 2) * 128 + lane * 4 + (j & 3)], hnew);
                sm_yb[jj * 32 + lane] = hnew;
            }
        }
        gbar(tgt);                               // h globally complete
        if (tid == 0 && t + 1 < NS) { expect_tx(mb, STATE_B); bulk_g2s(su32(sm_state), g_h, STATE_B, mb); }

        // coalesced y store from the bounce buffer
        for (int idx = tid; idx < 32 * JB; idx += 256) {
            const int b = idx / JB, jj = idx % JB;
            y[((size_t)(b * NS + t)) * H + J0 + jj] = sm_yb[jj * 32 + b];
        }
    }
}

// ------------------------- launch ------------------------------------------
extern "C" void kernel_launch(void* const* d_in, const int* in_sizes, int n_in,
                              void* d_out, int out_size)
{
    (void)in_sizes; (void)n_in; (void)out_size;
    const float* x   = (const float*)d_in[0];
    const float* Wi0 = (const float*)d_in[1];
    const float* Wh0 = (const float*)d_in[2];
    const float* bh0 = (const float*)d_in[3];
    const float* h00 = (const float*)d_in[4];
    const float* Wi1 = (const float*)d_in[5];
    const float* Wh1 = (const float*)d_in[6];
    const float* bh1 = (const float*)d_in[7];
    const float* h01 = (const float*)d_in[8];
    const float* Wi2 = (const float*)d_in[9];
    const float* Wh2 = (const float*)d_in[10];
    const float* bh2 = (const float*)d_in[11];
    const float* h02 = (const float*)d_in[12];
    const float* Wo  = (const float*)d_in[13];
    const float* bo  = (const float*)d_in[14];
    float* out = (float*)d_out;

    float *xg_p, *y0_p, *y1_p, *y2_p;
    cudaGetSymbolAddress((void**)&xg_p, g_xg);
    cudaGetSymbolAddress((void**)&y0_p, g_y0);
    cudaGetSymbolAddress((void**)&y1_p, g_y1);
    cudaGetSymbolAddress((void**)&y2_p, g_y2);

    const int SMEM512  = 32 * 512  * 4 + (3 * 4 * 32 + 4 * 2 * 32) * 4;   // 67072
    const int SMEM1024 = 32 * 1024 * 4 + (3 * 8 * 32 + 8 * 2 * 32) * 4;   // 136192
    cudaFuncSetAttribute(gru_scan<512>,  cudaFuncAttributeMaxDynamicSharedMemorySize, SMEM512);
    cudaFuncSetAttribute(gru_scan<1024>, cudaFuncAttributeMaxDynamicSharedMemorySize, SMEM1024);

    const int M = NB * NS;  // 16384

    // layer 0: 256 -> 512
    gemm_tn<false, true ><<<dim3(1536 / BN, M / BM), 256>>>(x, Wi0, bh0, xg_p, M, 1536, 256);
    gru_scan<512><<<NBLK, 256, SMEM512>>>(xg_p, Wh0, h00, y0_p);
    // layer 1: 512 -> 1024
    gemm_tn<false, true ><<<dim3(3072 / BN, M / BM), 256>>>(y0_p, Wi1, bh1, xg_p, M, 3072, 512);
    gru_scan<1024><<<NBLK, 256, SMEM1024>>>(xg_p, Wh1, h01, y1_p);
    // layer 2: 1024 -> 512
    gemm_tn<false, true ><<<dim3(1536 / BN, M / BM), 256>>>(y1_p, Wi2, bh2, xg_p, M, 1536, 1024);
    gru_scan<512><<<NBLK, 256, SMEM512>>>(xg_p, Wh2, h02, y2_p);
    // output head: 512 -> 256, ReLU, row-major
    gemm_tn<true, false><<<dim3(256 / BN, M / BM), 256>>>(y2_p, Wo, bo, out, M, 256, 512);
}